// round 2
// baseline (speedup 1.0000x reference)
#include <cuda_runtime.h>
#include <cuda_bf16.h>

#define Bx   16
#define Nn   1024
#define DINc 128
#define Hh   4
#define Dd   32
#define HD   128   // Hh*Dd

// Scratch (device globals — no allocation allowed in kernel_launch)
__device__ float    g_h [Bx*Nn*HD];          // 8.4 MB: h = x@W + b
__device__ float    g_ei[Bx*Nn*Hh];
__device__ float    g_ej[Bx*Nn*Hh];
__device__ unsigned g_am[(size_t)Bx*Nn*(Nn/32)];  // 2 MB packed adjacency bits

// ---------------------------------------------------------------------------
// Kernel 1: h = x @ W + b.  Block = 128 threads (one per output col), 32 rows.
// ---------------------------------------------------------------------------
__global__ void __launch_bounds__(128) k_gemm(const float* __restrict__ x,
                                              const float* __restrict__ W,
                                              const float* __restrict__ bias) {
    __shared__ float  Ws[DINc*HD];     // 64 KB
    __shared__ float4 xs4[32*32];      // 16 KB (32 rows x 128 floats)
    int c = threadIdx.x;               // output column 0..127
    size_t row0 = (size_t)blockIdx.x * 32;

    const float4* W4  = (const float4*)W;
    float4*       Ws4 = (float4*)Ws;
#pragma unroll
    for (int i = 0; i < 32; i++) Ws4[i*128 + c] = W4[i*128 + c];
    const float4* x4 = (const float4*)(x + row0*DINc);
    for (int i = c; i < 32*32; i += 128) xs4[i] = x4[i];
    __syncthreads();

    float acc[32];
#pragma unroll
    for (int r = 0; r < 32; r++) acc[r] = 0.f;

#pragma unroll 4
    for (int k = 0; k < DINc; k += 4) {
        float w0 = Ws[(k+0)*HD + c];
        float w1 = Ws[(k+1)*HD + c];
        float w2 = Ws[(k+2)*HD + c];
        float w3 = Ws[(k+3)*HD + c];
#pragma unroll
        for (int r = 0; r < 32; r++) {
            float4 xv = xs4[r*32 + (k >> 2)];   // broadcast LDS.128
            acc[r] = fmaf(xv.x, w0, fmaf(xv.y, w1, fmaf(xv.z, w2, fmaf(xv.w, w3, acc[r]))));
        }
    }
    float bc = bias[c];
#pragma unroll
    for (int r = 0; r < 32; r++) g_h[(row0 + r)*HD + c] = acc[r] + bc;
}

// ---------------------------------------------------------------------------
// Kernel 2: ei[row][h] = h[row,h,:]·a_i,  ej = h·a_j.  One warp per row.
// ---------------------------------------------------------------------------
__global__ void __launch_bounds__(256) k_edge(const float* __restrict__ a) {
    int gw   = (blockIdx.x*256 + threadIdx.x) >> 5;   // row 0..B*N-1
    int lane = threadIdx.x & 31;
    float ai = a[lane];          // a[:32,0]
    float aj = a[Dd + lane];     // a[32:64,0]
    const float* hr = g_h + (size_t)gw*HD;
#pragma unroll
    for (int hh = 0; hh < Hh; hh++) {
        float v  = hr[hh*32 + lane];
        float si = v*ai, sj = v*aj;
#pragma unroll
        for (int o = 16; o > 0; o >>= 1) {
            si += __shfl_xor_sync(0xffffffffu, si, o);
            sj += __shfl_xor_sync(0xffffffffu, sj, o);
        }
        if (lane == 0) { g_ei[gw*Hh + hh] = si; g_ej[gw*Hh + hh] = sj; }
    }
}

// ---------------------------------------------------------------------------
// Kernel 3: pack adj row bits.  One warp per (b,i) row, ballot over 32 j.
// ---------------------------------------------------------------------------
__global__ void __launch_bounds__(256) k_pack(const int* __restrict__ adj) {
    int row  = (blockIdx.x*256 + threadIdx.x) >> 5;
    int lane = threadIdx.x & 31;
    const int* ar = adj + (size_t)row*Nn;
#pragma unroll
    for (int wd = 0; wd < Nn/32; wd++) {
        unsigned mm = __ballot_sync(0xffffffffu, ar[wd*32 + lane] > 0);
        if (lane == 0) g_am[(size_t)row*(Nn/32) + wd] = mm;
    }
}

// ---------------------------------------------------------------------------
// Kernel 4: fused masked-softmax attention.
// Grid (N/32, B). Block 256 thr = 8 warps; warp owns 4 i-rows, all 4 heads.
// smem j-tile: h[b, j0:j0+128, :] (64 KB) reused across 32 i-rows.
// Softmax without max-subtraction (e bounded), masked -> p = 0.
// ---------------------------------------------------------------------------
__global__ void __launch_bounds__(256, 2) k_attn(float* __restrict__ out) {
    __shared__ float hs [128*HD];     // 64 KB
    __shared__ float ejs[Hh*128];     // transposed: ejs[hh][j]
    int tid  = threadIdx.x;
    int lane = tid & 31;
    int w    = tid >> 5;
    int b    = blockIdx.y;
    int ibase = blockIdx.x*32 + w*4;  // first of this warp's 4 i-rows

    float eir[4][Hh];
#pragma unroll
    for (int r = 0; r < 4; r++)
#pragma unroll
        for (int hh = 0; hh < Hh; hh++)
            eir[r][hh] = g_ei[((size_t)b*Nn + ibase + r)*Hh + hh];

    float acc[4][Hh], l[4][Hh];
#pragma unroll
    for (int r = 0; r < 4; r++)
#pragma unroll
        for (int hh = 0; hh < Hh; hh++) { acc[r][hh] = 0.f; l[r][hh] = 0.f; }

    const float* hb = g_h + (size_t)b*Nn*HD;

    for (int jt = 0; jt < Nn/128; jt++) {
        __syncthreads();
        // stage h tile (contiguous 128*128 floats) and ej tile
        const float4* src = (const float4*)(hb + (size_t)jt*128*HD);
        float4*       dst = (float4*)hs;
#pragma unroll
        for (int t = 0; t < 16; t++) dst[tid + t*256] = src[tid + t*256];
        for (int t = tid; t < 512; t += 256) {
            int j = t >> 2, hh = t & 3;
            ejs[hh*128 + j] = g_ej[((size_t)b*Nn + jt*128 + j)*Hh + hh];
        }
        __syncthreads();

#pragma unroll 1
        for (int js = 0; js < 4; js++) {       // 32-j sub-tiles
            unsigned m[4];
#pragma unroll
            for (int r = 0; r < 4; r++)
                m[r] = g_am[((size_t)b*Nn + ibase + r)*(Nn/32) + jt*4 + js];

#pragma unroll 1
            for (int hh = 0; hh < Hh; hh++) {
                // h column for lane=d across 32 j's -> registers
                float hv[32];
#pragma unroll
                for (int jj = 0; jj < 32; jj++)
                    hv[jj] = hs[(js*32 + jj)*HD + hh*32 + lane];

                float ejv = ejs[hh*128 + js*32 + lane];  // lane = jj role
#pragma unroll
                for (int r = 0; r < 4; r++) {
                    // p-phase: lane jj computes one edge weight
                    float e = eir[r][hh] + ejv;
                    e = e > 0.f ? e : 0.2f*e;
                    float p = ((m[r] >> lane) & 1u) ? __expf(e) : 0.f;
                    // denominator via butterfly reduce (all lanes get sum)
                    float s = p;
#pragma unroll
                    for (int o = 16; o > 0; o >>= 1)
                        s += __shfl_xor_sync(0xffffffffu, s, o);
                    l[r][hh] += s;
                    // accumulate: lane=d, broadcast p_jj via shfl
                    float a = acc[r][hh];
#pragma unroll
                    for (int jj = 0; jj < 32; jj++)
                        a = fmaf(__shfl_sync(0xffffffffu, p, jj), hv[jj], a);
                    acc[r][hh] = a;
                }
            }
        }
    }

#pragma unroll
    for (int r = 0; r < 4; r++) {
        float* orow = out + ((size_t)b*Nn + ibase + r)*HD;
#pragma unroll
        for (int hh = 0; hh < Hh; hh++)
            orow[hh*32 + lane] = acc[r][hh] / l[r][hh];
    }
}

// ---------------------------------------------------------------------------
extern "C" void kernel_launch(void* const* d_in, const int* in_sizes, int n_in,
                              void* d_out, int out_size) {
    const float* x = nullptr; const int* adj = nullptr;
    const float* W = nullptr; const float* bias = nullptr; const float* a = nullptr;
    for (int i = 0; i < n_in; i++) {
        switch (in_sizes[i]) {
            case Bx*Nn*DINc: x    = (const float*)d_in[i]; break;  // 2097152
            case Bx*Nn*Nn:   adj  = (const int*)  d_in[i]; break;  // 16777216
            case DINc*HD:    W    = (const float*)d_in[i]; break;  // 16384
            case HD:         bias = (const float*)d_in[i]; break;  // 128
            case 2*Dd:       a    = (const float*)d_in[i]; break;  // 64
        }
    }
    k_gemm<<<Bx*Nn/32, 128>>>(x, W, bias);
    k_edge<<<Bx*Nn/8, 256>>>(a);
    k_pack<<<Bx*Nn/8, 256>>>(adj);
    k_attn<<<dim3(Nn/32, Bx), 256>>>((float*)d_out);
}

// round 3
// speedup vs baseline: 1.5823x; 1.5823x over previous
#include <cuda_runtime.h>
#include <cuda_bf16.h>

#define Bx   16
#define Nn   1024
#define DINc 128
#define Hh   4
#define Dd   32
#define HD   128   // Hh*Dd

// Scratch (device globals — no allocation allowed in kernel_launch)
__device__ float    g_h [Bx*Nn*HD];          // 8.4 MB: h = x@W + b
__device__ float    g_ei[Bx*Nn*Hh];
__device__ float    g_ej[Bx*Nn*Hh];
__device__ unsigned g_am[(size_t)Bx*Nn*(Nn/32)];  // 2 MB packed adjacency bits

// ---------------------------------------------------------------------------
// Kernel 1: h = x @ W + b.  Block = 128 threads (one per output col), 32 rows.
// ---------------------------------------------------------------------------
__global__ void __launch_bounds__(128) k_gemm(const float* __restrict__ x,
                                              const float* __restrict__ W,
                                              const float* __restrict__ bias) {
    __shared__ float  Ws[DINc*HD];     // 64 KB
    __shared__ float4 xs4[32*32];      // 16 KB (32 rows x 128 floats)
    int c = threadIdx.x;               // output column 0..127
    size_t row0 = (size_t)blockIdx.x * 32;

    const float4* W4  = (const float4*)W;
    float4*       Ws4 = (float4*)Ws;
#pragma unroll
    for (int i = 0; i < 32; i++) Ws4[i*128 + c] = W4[i*128 + c];
    const float4* x4 = (const float4*)(x + row0*DINc);
    for (int i = c; i < 32*32; i += 128) xs4[i] = x4[i];
    __syncthreads();

    float acc[32];
#pragma unroll
    for (int r = 0; r < 32; r++) acc[r] = 0.f;

#pragma unroll 4
    for (int k = 0; k < DINc; k += 4) {
        float w0 = Ws[(k+0)*HD + c];
        float w1 = Ws[(k+1)*HD + c];
        float w2 = Ws[(k+2)*HD + c];
        float w3 = Ws[(k+3)*HD + c];
#pragma unroll
        for (int r = 0; r < 32; r++) {
            float4 xv = xs4[r*32 + (k >> 2)];   // broadcast LDS.128
            acc[r] = fmaf(xv.x, w0, fmaf(xv.y, w1, fmaf(xv.z, w2, fmaf(xv.w, w3, acc[r]))));
        }
    }
    float bc = bias[c];
#pragma unroll
    for (int r = 0; r < 32; r++) g_h[(row0 + r)*HD + c] = acc[r] + bc;
}

// ---------------------------------------------------------------------------
// Kernel 2: ei[row][h] = h[row,h,:]·a_i,  ej = h·a_j.  One warp per row.
// ---------------------------------------------------------------------------
__global__ void __launch_bounds__(256) k_edge(const float* __restrict__ a) {
    int gw   = (blockIdx.x*256 + threadIdx.x) >> 5;   // row 0..B*N-1
    int lane = threadIdx.x & 31;
    float ai = a[lane];          // a[:32,0]
    float aj = a[Dd + lane];     // a[32:64,0]
    const float* hr = g_h + (size_t)gw*HD;
#pragma unroll
    for (int hh = 0; hh < Hh; hh++) {
        float v  = hr[hh*32 + lane];
        float si = v*ai, sj = v*aj;
#pragma unroll
        for (int o = 16; o > 0; o >>= 1) {
            si += __shfl_xor_sync(0xffffffffu, si, o);
            sj += __shfl_xor_sync(0xffffffffu, sj, o);
        }
        if (lane == 0) { g_ei[gw*Hh + hh] = si; g_ej[gw*Hh + hh] = sj; }
    }
}

// ---------------------------------------------------------------------------
// Kernel 3: pack adj row bits.  One warp per (b,i) row, ballot over 32 j.
// ---------------------------------------------------------------------------
__global__ void __launch_bounds__(256) k_pack(const int* __restrict__ adj) {
    int row  = (blockIdx.x*256 + threadIdx.x) >> 5;
    int lane = threadIdx.x & 31;
    const int* ar = adj + (size_t)row*Nn;
#pragma unroll
    for (int wd = 0; wd < Nn/32; wd++) {
        unsigned mm = __ballot_sync(0xffffffffu, ar[wd*32 + lane] > 0);
        if (lane == 0) g_am[(size_t)row*(Nn/32) + wd] = mm;
    }
}

// ---------------------------------------------------------------------------
// Kernel 4 (v2): fused masked-softmax attention, two-phase smem GEMM.
// Grid (N/32, B). Block 256 = 8 warps. Block owns 32 i-rows, all 4 heads.
//
// Per 32-j tile:
//   Phase A: compute P tile into smem ps[j][hh][i] (lane = i, warp owns 4 j),
//            denominators accumulated in registers per-lane (lane == row).
//   Phase B: register-blocked GEMM: thread owns 4 i-rows x 4 d-cols. Per j:
//            1 LDS.128 (p pair-of-f32x2, contiguous in i) + 1 LDS.128 (h4)
//            + 8 fma.rn.f32x2 (packed over the i-pairs).
// Softmax without max-subtraction (e bounded); masked edges -> p = 0.
// ---------------------------------------------------------------------------
__global__ void __launch_bounds__(256) k_attn(float* __restrict__ out) {
    __shared__ __align__(16) float hs[32*128];   // 16 KB  hs[j*128 + d]
    __shared__ __align__(16) float ps[32*144];   // 18 KB  ps[j*144 + hh*36 + i]
    __shared__ float lsp[32*32];                 //  4 KB  partial denoms [w*4+hh][i]
    __shared__ float lfin[32*4];                 // reciprocal denom [i][hh]

    const int tid  = threadIdx.x;
    const int lane = tid & 31;
    const int w    = tid >> 5;
    const int b    = blockIdx.y;
    const int i0   = blockIdx.x * 32;
    const size_t bN = (size_t)b * Nn;

    // ---- phase-A constants: lane plays role of i (row i0+lane) ----
    const float4 ei4 = *(const float4*)&g_ei[(bN + i0 + lane)*Hh];
    const float eir[4] = {ei4.x, ei4.y, ei4.z, ei4.w};
    float lreg[4] = {0.f, 0.f, 0.f, 0.f};
    const unsigned* amrow = g_am + (bN + i0 + lane)*(Nn/32);

    // ---- phase-B ids: thread owns rows i_t*4..+3, cols d_t*4..+3 ----
    const int i_t = w;
    const int d_t = lane;
    const int hhB = d_t >> 3;          // head of this thread's 4 columns

    unsigned long long acc[8];         // acc[c*2+p]: col c, i-pair p (f32x2)
#pragma unroll
    for (int k = 0; k < 8; k++) acc[k] = 0ull;

    const float* hb = g_h + bN*HD;

    for (int jt = 0; jt < Nn/32; jt++) {
        __syncthreads();               // previous phase B done with hs/ps
        // load h tile: 32 rows x 128 cols (contiguous)
        {
            const float4* src = (const float4*)(hb + (size_t)jt*32*HD);
            float4*       dst = (float4*)hs;
#pragma unroll
            for (int t = 0; t < 4; t++) dst[tid + t*256] = src[tid + t*256];
        }
        // phase A: warp w computes p for jj = 4w..4w+3, lane = i
        {
            const unsigned mword = amrow[jt];
#pragma unroll
            for (int q = 0; q < 4; q++) {
                const int jj = w*4 + q;
                const float4 ej4 = *(const float4*)&g_ej[(bN + (size_t)jt*32 + jj)*Hh];
                const float ejv[4] = {ej4.x, ej4.y, ej4.z, ej4.w};
                const bool mb = (mword >> jj) & 1u;
#pragma unroll
                for (int hh = 0; hh < 4; hh++) {
                    float e = eir[hh] + ejv[hh];
                    e = fmaxf(e, 0.2f*e);               // leaky relu
                    float p = mb ? __expf(e) : 0.f;
                    lreg[hh] += p;
                    ps[jj*144 + hh*36 + lane] = p;
                }
            }
        }
        __syncthreads();
        // phase B: out-tile accumulate from smem
        {
            const float* psB = ps + hhB*36 + i_t*4;
            const float* hsB = hs + d_t*4;
#pragma unroll 4
            for (int j = 0; j < 32; j++) {
                const longlong2 pv = *(const longlong2*)(psB + j*144);
                const float4    h4 = *(const float4*)(hsB + j*128);
                const unsigned long long p01 = (unsigned long long)pv.x;
                const unsigned long long p23 = (unsigned long long)pv.y;
                unsigned long long hd0, hd1, hd2, hd3;
                asm("mov.b64 %0, {%1, %1};" : "=l"(hd0) : "f"(h4.x));
                asm("mov.b64 %0, {%1, %1};" : "=l"(hd1) : "f"(h4.y));
                asm("mov.b64 %0, {%1, %1};" : "=l"(hd2) : "f"(h4.z));
                asm("mov.b64 %0, {%1, %1};" : "=l"(hd3) : "f"(h4.w));
                asm("fma.rn.f32x2 %0, %1, %2, %0;" : "+l"(acc[0]) : "l"(p01), "l"(hd0));
                asm("fma.rn.f32x2 %0, %1, %2, %0;" : "+l"(acc[1]) : "l"(p23), "l"(hd0));
                asm("fma.rn.f32x2 %0, %1, %2, %0;" : "+l"(acc[2]) : "l"(p01), "l"(hd1));
                asm("fma.rn.f32x2 %0, %1, %2, %0;" : "+l"(acc[3]) : "l"(p23), "l"(hd1));
                asm("fma.rn.f32x2 %0, %1, %2, %0;" : "+l"(acc[4]) : "l"(p01), "l"(hd2));
                asm("fma.rn.f32x2 %0, %1, %2, %0;" : "+l"(acc[5]) : "l"(p23), "l"(hd2));
                asm("fma.rn.f32x2 %0, %1, %2, %0;" : "+l"(acc[6]) : "l"(p01), "l"(hd3));
                asm("fma.rn.f32x2 %0, %1, %2, %0;" : "+l"(acc[7]) : "l"(p23), "l"(hd3));
            }
        }
    }

    // ---- reduce denominators across warps (each warp has partial over its j's)
#pragma unroll
    for (int hh = 0; hh < 4; hh++) lsp[(w*4 + hh)*32 + lane] = lreg[hh];
    __syncthreads();
    if (tid < 128) {
        int i = tid >> 2, hh = tid & 3;
        float s = 0.f;
#pragma unroll
        for (int ww = 0; ww < 8; ww++) s += lsp[(ww*4 + hh)*32 + i];
        lfin[i*4 + hh] = 1.f / s;
    }
    __syncthreads();

    // ---- write output: 4 rows x float4 per thread, fully coalesced
#pragma unroll
    for (int r = 0; r < 4; r++) {
        const int row = i_t*4 + r;
        const float rv = lfin[row*4 + hhB];
        float v[4];
#pragma unroll
        for (int c = 0; c < 4; c++) {
            float lo, hi;
            asm("mov.b64 {%0, %1}, %2;" : "=f"(lo), "=f"(hi) : "l"(acc[c*2 + (r >> 1)]));
            v[c] = ((r & 1) ? hi : lo) * rv;
        }
        float4 o = {v[0], v[1], v[2], v[3]};
        *(float4*)&out[(bN + i0 + row)*HD + d_t*4] = o;
    }
}

// ---------------------------------------------------------------------------
extern "C" void kernel_launch(void* const* d_in, const int* in_sizes, int n_in,
                              void* d_out, int out_size) {
    const float* x = nullptr; const int* adj = nullptr;
    const float* W = nullptr; const float* bias = nullptr; const float* a = nullptr;
    for (int i = 0; i < n_in; i++) {
        switch (in_sizes[i]) {
            case Bx*Nn*DINc: x    = (const float*)d_in[i]; break;  // 2097152
            case Bx*Nn*Nn:   adj  = (const int*)  d_in[i]; break;  // 16777216
            case DINc*HD:    W    = (const float*)d_in[i]; break;  // 16384
            case HD:         bias = (const float*)d_in[i]; break;  // 128
            case 2*Dd:       a    = (const float*)d_in[i]; break;  // 64
        }
    }
    k_gemm<<<Bx*Nn/32, 128>>>(x, W, bias);
    k_edge<<<Bx*Nn/8, 256>>>(a);
    k_pack<<<Bx*Nn/8, 256>>>(adj);
    k_attn<<<dim3(Nn/32, Bx), 256>>>((float*)d_out);
}

// round 5
// speedup vs baseline: 5.7939x; 3.6617x over previous
#include <cuda_runtime.h>
#include <cuda_bf16.h>
#include <cstdint>

#define Bx   16
#define Nn   1024
#define DINc 128
#define Hh   4
#define Dd   32
#define HD   128
#define BN   (Bx*Nn)
#define LOG2E 1.4426950408889634f

// ---------------------------------------------------------------------------
// Scratch (device globals — no allocation allowed in kernel_launch)
// ---------------------------------------------------------------------------
__device__ float    g_hT[(size_t)Bx*Hh*Nn*Dd];   // 8.4 MB tf32-rounded, [b][hh][j][d]
__device__ float    g_ei[(size_t)Hh*BN];         // [hh][row], pre-scaled by log2(e)
__device__ float    g_ej[(size_t)Hh*BN];
__device__ unsigned g_am[(size_t)32*BN];         // [jt][row] packed adjacency bits

__device__ __forceinline__ float tf32r(float x) {
    uint32_t u; asm("cvt.rna.tf32.f32 %0, %1;" : "=r"(u) : "f"(x));
    return __uint_as_float(u);
}

// ---------------------------------------------------------------------------
// Kernel 1: h = x@W + b  ->  g_hT (tf32, [b][hh][j][d])  + fused ei/ej.
// Block = 128 threads (thread c = (hh = c>>5, d = c&31)), 32 rows per block.
// warp == head, so the ei/ej reduction over d is a plain warp butterfly.
// ---------------------------------------------------------------------------
__global__ void __launch_bounds__(128) k_gemm(const float* __restrict__ x,
                                              const float* __restrict__ W,
                                              const float* __restrict__ bias,
                                              const float* __restrict__ a) {
    __shared__ float  Ws[DINc*HD];     // 64 KB
    __shared__ float4 xs4[32*32];      // 16 KB (32 rows x 128 floats)
    const int c = threadIdx.x;
    const size_t row0 = (size_t)blockIdx.x * 32;

    const float4* W4  = (const float4*)W;
    float4*       Ws4 = (float4*)Ws;
#pragma unroll
    for (int i = 0; i < 32; i++) Ws4[i*128 + c] = W4[i*128 + c];
    const float4* x4 = (const float4*)(x + row0*DINc);
    for (int i = c; i < 32*32; i += 128) xs4[i] = x4[i];
    __syncthreads();

    float acc[32];
#pragma unroll
    for (int r = 0; r < 32; r++) acc[r] = 0.f;

#pragma unroll 4
    for (int k = 0; k < DINc; k += 4) {
        float w0 = Ws[(k+0)*HD + c];
        float w1 = Ws[(k+1)*HD + c];
        float w2 = Ws[(k+2)*HD + c];
        float w3 = Ws[(k+3)*HD + c];
#pragma unroll
        for (int r = 0; r < 32; r++) {
            float4 xv = xs4[r*32 + (k >> 2)];
            acc[r] = fmaf(xv.x, w0, fmaf(xv.y, w1, fmaf(xv.z, w2, fmaf(xv.w, w3, acc[r]))));
        }
    }
    const int d  = c & 31, hh = c >> 5;
    const float bc = bias[c];
#pragma unroll
    for (int r = 0; r < 32; r++) acc[r] += bc;

    // ---- fused edge logits: ei = h·a_i, ej = h·a_j (reduce over d = lanes)
    {
        const float ai = a[d];
        const float aj = a[Dd + d];
#pragma unroll
        for (int r = 0; r < 32; r++) {
            float si = acc[r]*ai, sj = acc[r]*aj;
#pragma unroll
            for (int o = 16; o > 0; o >>= 1) {
                si += __shfl_xor_sync(0xffffffffu, si, o);
                sj += __shfl_xor_sync(0xffffffffu, sj, o);
            }
            if (d == 0) {
                g_ei[(size_t)hh*BN + row0 + r] = si * LOG2E;
                g_ej[(size_t)hh*BN + row0 + r] = sj * LOG2E;
            }
        }
    }

    // ---- g_hT: this block covers one (b, jt) tile of 32 j-rows.
    const int b  = (int)(row0 >> 10);
    const int jt = (int)((row0 >> 5) & 31);
    float* ht = g_hT + (((size_t)b*Hh + hh) << 15) + ((size_t)jt*32 << 5) + d;
#pragma unroll
    for (int r = 0; r < 32; r++) ht[r*32] = tf32r(acc[r]);
}

// ---------------------------------------------------------------------------
// Kernel 2: pack adj bits, layout [jt-word][row] so k_attn loads coalesced.
// ---------------------------------------------------------------------------
__global__ void __launch_bounds__(256) k_pack(const int* __restrict__ adj) {
    int row  = (blockIdx.x*256 + threadIdx.x) >> 5;
    int lane = threadIdx.x & 31;
    const int* ar = adj + (size_t)row*Nn;
#pragma unroll
    for (int wd = 0; wd < Nn/32; wd++) {
        unsigned mm = __ballot_sync(0xffffffffu, ar[wd*32 + lane] > 0);
        if (lane == 0) g_am[(size_t)wd*BN + row] = mm;
    }
}

// ---------------------------------------------------------------------------
// Kernel 3: flash attention via mma.sync.m16n8k8 tf32.
// Grid (8 i-tiles, Hh, Bx), 128 threads = 4 warps; warp owns 32 i-rows.
// P computed straight into A-fragment registers (no smem for P).
// h tile (32j x 32d) staged in double-buffered smem, one bar.sync per jt.
// ---------------------------------------------------------------------------
__global__ void __launch_bounds__(128) k_attn(float* __restrict__ out) {
    __shared__ float    ejs[Nn];          // 4 KB
    __shared__ unsigned ams[32*128];      // 16 KB  [jt][rlocal]
    __shared__ float    hs[2][32*36];     // 9.2 KB padded [j][d]

    const int tid  = threadIdx.x;
    const int lane = tid & 31;
    const int w    = tid >> 5;
    const int qid  = lane >> 2;           // 0..7
    const int tq   = lane & 3;            // 0..3
    const int hh   = blockIdx.y;
    const int b    = blockIdx.z;
    const int i0   = blockIdx.x * 128;
    const size_t bN = (size_t)b * Nn;

    // stage ej + masks for the whole block
    {
        const float* ejsrc = g_ej + (size_t)hh*BN + bN;
        for (int k = tid; k < Nn; k += 128) ejs[k] = ejsrc[k];
        const unsigned* amsrc = g_am + bN + i0;
        for (int k = tid; k < 32*128; k += 128)
            ams[k] = amsrc[(size_t)(k >> 7)*BN + (k & 127)];
    }

    float eir[4], lden[4];
#pragma unroll
    for (int m = 0; m < 4; m++) {
        eir[m]  = g_ei[(size_t)hh*BN + bN + i0 + w*32 + qid + 8*m];
        lden[m] = 0.f;
    }

    float acc[2][4][4];
#pragma unroll
    for (int mt = 0; mt < 2; mt++)
#pragma unroll
        for (int nt = 0; nt < 4; nt++)
#pragma unroll
            for (int k = 0; k < 4; k++) acc[mt][nt][k] = 0.f;

    const float* htsrc = g_hT + (((size_t)b*Hh + hh) << 15);
    const float4* hsrc4 = (const float4*)htsrc;
    float4 hv0 = hsrc4[tid];
    float4 hv1 = hsrc4[tid + 128];
    __syncthreads();   // ejs/ams visible

    for (int jt = 0; jt < 32; jt++) {
        const int buf = jt & 1;
        // store prefetched h tile (padded rows: j = idx/8, d0 = (idx%8)*4)
        {
            float* hd0 = &hs[buf][(tid >> 3)*36 + (tid & 7)*4];
            float* hd1 = &hs[buf][((tid + 128) >> 3)*36 + (tid & 7)*4];
            *(float4*)hd0 = hv0;
            *(float4*)hd1 = hv1;
        }
        __syncthreads();
        if (jt < 31) {
            const float4* nx = (const float4*)(htsrc + (size_t)(jt + 1)*1024);
            hv0 = nx[tid]; hv1 = nx[tid + 128];
        }

        // ---- phase A: P in A-fragment layout
        const float* ej = ejs + jt*32;
        float ejv[8];
#pragma unroll
        for (int t = 0; t < 8; t++) ejv[t] = ej[tq + 4*t];
        unsigned mw[4];
#pragma unroll
        for (int m = 0; m < 4; m++) mw[m] = ams[jt*128 + w*32 + qid + 8*m];

        uint32_t pu[4][8];
#pragma unroll
        for (int m = 0; m < 4; m++) {
            const float ei = eir[m];
#pragma unroll
            for (int t = 0; t < 8; t++) {
                float e = ei + ejv[t];
                e = fmaxf(e, 0.2f*e);                       // leaky relu (log2-scaled)
                e = ((mw[m] >> (tq + 4*t)) & 1u) ? e : -10000.f;
                float p; asm("ex2.approx.ftz.f32 %0, %1;" : "=f"(p) : "f"(e));
                lden[m] += p;
                asm("cvt.rna.tf32.f32 %0, %1;" : "=r"(pu[m][t]) : "f"(p));
            }
        }

        // ---- phase B: 32 x m16n8k8 tf32 mma
#pragma unroll
        for (int ks = 0; ks < 4; ks++) {
            const float* hrow0 = &hs[buf][(ks*8 + tq)*36 + qid];
            const float* hrow1 = hrow0 + 4*36;
            uint32_t b0[4], b1[4];
#pragma unroll
            for (int nt = 0; nt < 4; nt++) {
                b0[nt] = __float_as_uint(hrow0[nt*8]);
                b1[nt] = __float_as_uint(hrow1[nt*8]);
            }
#pragma unroll
            for (int mt = 0; mt < 2; mt++) {
                const uint32_t a0 = pu[2*mt  ][2*ks  ];
                const uint32_t a1 = pu[2*mt+1][2*ks  ];
                const uint32_t a2 = pu[2*mt  ][2*ks+1];
                const uint32_t a3 = pu[2*mt+1][2*ks+1];
#pragma unroll
                for (int nt = 0; nt < 4; nt++) {
                    asm("mma.sync.aligned.m16n8k8.row.col.f32.tf32.tf32.f32 "
                        "{%0,%1,%2,%3}, {%4,%5,%6,%7}, {%8,%9}, {%0,%1,%2,%3};"
                        : "+f"(acc[mt][nt][0]), "+f"(acc[mt][nt][1]),
                          "+f"(acc[mt][nt][2]), "+f"(acc[mt][nt][3])
                        : "r"(a0), "r"(a1), "r"(a2), "r"(a3),
                          "r"(b0[nt]), "r"(b1[nt]));
                }
            }
        }
    }

    // ---- finish denominators (sum the 4 j-phase lanes) and store
#pragma unroll
    for (int m = 0; m < 4; m++) {
        lden[m] += __shfl_xor_sync(0xffffffffu, lden[m], 1);
        lden[m] += __shfl_xor_sync(0xffffffffu, lden[m], 2);
        lden[m] = 1.f / lden[m];
    }
#pragma unroll
    for (int mt = 0; mt < 2; mt++) {
#pragma unroll
        for (int half = 0; half < 2; half++) {
            const int m = 2*mt + half;
            const int grow = i0 + w*32 + mt*16 + qid + 8*half;
            const float rl = lden[m];
            float* orow = out + (bN + grow)*HD + hh*32 + tq*2;
#pragma unroll
            for (int nt = 0; nt < 4; nt++) {
                float2 v = { acc[mt][nt][half*2 + 0]*rl, acc[mt][nt][half*2 + 1]*rl };
                *(float2*)(orow + nt*8) = v;
            }
        }
    }
}

// ---------------------------------------------------------------------------
extern "C" void kernel_launch(void* const* d_in, const int* in_sizes, int n_in,
                              void* d_out, int out_size) {
    const float* x = nullptr; const int* adj = nullptr;
    const float* W = nullptr; const float* bias = nullptr; const float* a = nullptr;
    for (int i = 0; i < n_in; i++) {
        switch (in_sizes[i]) {
            case Bx*Nn*DINc: x    = (const float*)d_in[i]; break;
            case Bx*Nn*Nn:   adj  = (const int*)  d_in[i]; break;
            case DINc*HD:    W    = (const float*)d_in[i]; break;
            case HD:         bias = (const float*)d_in[i]; break;
            case 2*Dd:       a    = (const float*)d_in[i]; break;
        }
    }
    k_gemm<<<BN/32, 128>>>(x, W, bias, a);
    k_pack<<<BN/8, 256>>>(adj);
    k_attn<<<dim3(8, Hh, Bx), 128>>>((float*)d_out);
}